// round 15
// baseline (speedup 1.0000x reference)
#include <cuda_runtime.h>

#define TT   1024
#define BB   16
#define CC   1024
#define HH   16
#define KW   7
#define PADL 6
#define MM   (TT * BB)       // 16384
#define NN   (HH * KW)       // 112
#define KD   1024
#define DENSE_BYTES ((size_t)BB * HH * TT * TT * 4) // 1 GiB

// softmaxed conv weights, [m = t*16+b][o = h*7+k]
__device__ float g_wsm[(size_t)MM * NN];

// ---------------------------------------------------------------------------
// tf32 helpers
// ---------------------------------------------------------------------------
__device__ __forceinline__ unsigned f2tf(float v) {
    unsigned r; asm("cvt.rna.tf32.f32 %0, %1;" : "=r"(r) : "f"(v)); return r;
}
__device__ __forceinline__ void split_tf32(float v, unsigned& hi, unsigned& lo) {
    hi = f2tf(v);
    lo = f2tf(v - __uint_as_float(hi));
}
__device__ __forceinline__ void mma_tf32(float* c, const unsigned* a, const unsigned* b) {
    asm volatile(
        "mma.sync.aligned.m16n8k8.row.col.f32.tf32.tf32.f32 "
        "{%0,%1,%2,%3}, {%4,%5,%6,%7}, {%8,%9}, {%0,%1,%2,%3};"
        : "+f"(c[0]), "+f"(c[1]), "+f"(c[2]), "+f"(c[3])
        : "r"(a[0]), "r"(a[1]), "r"(a[2]), "r"(a[3]), "r"(b[0]), "r"(b[1]));
}

// ---------------------------------------------------------------------------
// Tensor-core GEMM  w = x @ W^T (16384 x 112 x 1024), 3xTF32 for fp32
// accuracy, fused masked softmax over K=7 -> g_wsm.
// 4 warps/block; warp w owns m-tile [blockIdx*64 + 16w, +16) x all 112 cols.
// ---------------------------------------------------------------------------
__global__ __launch_bounds__(128)
void k_gemm_softmax_tc(const float* __restrict__ x,
                       const float* __restrict__ W)
{
    __shared__ float sC[4][16][113];           // per-warp slab, 28.9 KB

    const int lane = threadIdx.x & 31;
    const int wid  = threadIdx.x >> 5;
    const int m0   = blockIdx.x * 64 + wid * 16;
    const int gid  = lane >> 2;                // group id 0..7
    const int tig  = lane & 3;                 // thread-in-group 0..3

    float c[14][4];
#pragma unroll
    for (int j = 0; j < 14; j++)
#pragma unroll
        for (int r = 0; r < 4; r++) c[j][r] = 0.f;

    const float* pa = x + (size_t)(m0 + gid) * KD + tig;

#pragma unroll 1
    for (int k0 = 0; k0 < KD; k0 += 8) {
        // ---- A fragment (16x8, row-major) hi/lo ----
        float a0f = pa[k0];
        float a1f = pa[8 * KD + k0];
        float a2f = pa[k0 + 4];
        float a3f = pa[8 * KD + k0 + 4];
        unsigned ahi[4], alo[4];
        split_tf32(a0f, ahi[0], alo[0]);
        split_tf32(a1f, ahi[1], alo[1]);
        split_tf32(a2f, ahi[2], alo[2]);
        split_tf32(a3f, ahi[3], alo[3]);

#pragma unroll
        for (int j = 0; j < 14; j++) {
            // ---- B fragment (8x8, col-major: B[k][n] = W[n][k]) hi/lo ----
            const float* pw = W + (size_t)(j * 8 + gid) * KD + k0 + tig;
            float b0f = pw[0];
            float b1f = pw[4];
            unsigned bhi[2], blo[2];
            split_tf32(b0f, bhi[0], blo[0]);
            split_tf32(b1f, bhi[1], blo[1]);

            mma_tf32(c[j], ahi, bhi);
            mma_tf32(c[j], ahi, blo);
            mma_tf32(c[j], alo, bhi);
        }
    }

    // ---- epilogue: dump fragments to the warp's smem slab ----
#pragma unroll
    for (int j = 0; j < 14; j++) {
        sC[wid][gid    ][j * 8 + 2 * tig    ] = c[j][0];
        sC[wid][gid    ][j * 8 + 2 * tig + 1] = c[j][1];
        sC[wid][gid + 8][j * 8 + 2 * tig    ] = c[j][2];
        sC[wid][gid + 8][j * 8 + 2 * tig + 1] = c[j][3];
    }
    __syncwarp();

    // ---- masked softmax: 8 (row, head) pairs per lane ----
#pragma unroll
    for (int i = 0; i < 8; i++) {
        int p   = i * 32 + lane;               // 0..255
        int row = p >> 4;
        int h   = p & 15;
        int m   = m0 + row;
        int t   = m >> 4;

        const float* fr = &sC[wid][row][h * 7];
        int kmin = PADL - t; if (kmin < 0) kmin = 0;

        float mx = -1e30f;
#pragma unroll
        for (int k = 0; k < 7; k++)
            if (k >= kmin && fr[k] > mx) mx = fr[k];

        float e[7], s = 0.f;
#pragma unroll
        for (int k = 0; k < 7; k++) {
            e[k] = (k >= kmin) ? __expf(fr[k] - mx) : 0.f;
            s += e[k];
        }
        float inv = 1.f / s;
        float* gp = &g_wsm[(size_t)m * NN + h * 7];
#pragma unroll
        for (int k = 0; k < 7; k++)
            gp[k] = e[k] * inv;
    }
}

// ---------------------------------------------------------------------------
// k_out_band: eight consecutive t per block; 14 gather loads feed 8 outputs,
// plus the band scatter for those rows (dense already zeroed by memset).
// ---------------------------------------------------------------------------
__global__ __launch_bounds__(256)
void k_out_band(const float* __restrict__ x,
                float* __restrict__ out,
                float* __restrict__ dense)
{
    const int t0  = blockIdx.x * 8;
    const int b   = blockIdx.y;
    const int tid = threadIdx.x;

    __shared__ float sw[8 * NN];
    for (int e = tid; e < 8 * NN; e += 256) {
        int r = e / NN, idx = e - r * NN;
        sw[e] = g_wsm[(size_t)((t0 + r) * BB + b) * NN + idx];
    }
    __syncthreads();

    const int h = tid >> 4;
    const float4* x4 = (const float4*)x;

    float4 v[14];
#pragma unroll
    for (int k = 0; k < 14; k++) {
        int pos = t0 - PADL + k;
        if (pos < 0) pos = 0;               // weight is exactly 0 there
        v[k] = x4[((size_t)(pos * BB + b) << 8) + tid];
    }

    float4* out4 = (float4*)out;
#pragma unroll
    for (int r = 0; r < 8; r++) {
        const float* wr = &sw[r * NN + h * 7];
        float4 a = make_float4(0.f, 0.f, 0.f, 0.f);
#pragma unroll
        for (int k = 0; k < 7; k++) {
            float wk = wr[k];
            a.x += wk * v[r + k].x;
            a.y += wk * v[r + k].y;
            a.z += wk * v[r + k].z;
            a.w += wk * v[r + k].w;
        }
        out4[((size_t)((t0 + r) * BB + b) << 8) + tid] = a;
    }

    // band scatter for the 8 rows (zeros already laid by memset)
    for (int e = tid; e < 8 * NN; e += 256) {
        int r   = e / NN, idx = e - r * NN;
        int hh  = idx / 7;
        int k   = idx - hh * 7;
        int t   = t0 + r;
        int col = t - PADL + k;
        if (col >= 0)
            dense[((size_t)(b * HH + hh) << 20) + ((size_t)t << 10) + col] = sw[e];
    }
}

// ---------------------------------------------------------------------------
// Serial: tc-gemm -> memset(dense) -> k_out_band.
// ---------------------------------------------------------------------------
extern "C" void kernel_launch(void* const* d_in, const int* in_sizes, int n_in,
                              void* d_out, int out_size)
{
    const float* x = (const float*)d_in[0];   // (T, B, C) fp32
    const float* W = (const float*)d_in[1];   // (H*K, C)  fp32
    float* out   = (float*)d_out;
    float* dense = out + (size_t)MM * CC;

    k_gemm_softmax_tc<<<MM / 64, 128>>>(x, W);
    cudaMemsetAsync(dense, 0, DENSE_BYTES);
    dim3 g2(TT / 8, BB);
    k_out_band<<<g2, 256>>>(x, out, dense);
}

// round 16
// speedup vs baseline: 1.2026x; 1.2026x over previous
#include <cuda_runtime.h>

#define TT   1024
#define BB   16
#define CC   1024
#define HH   16
#define KW   7
#define PADL 6
#define MM   (TT * BB)       // 16384
#define NN   (HH * KW)       // 112
#define KD   1024
#define DENSE_BYTES ((size_t)BB * HH * TT * TT * 4) // 1 GiB

#define BM   64
#define BK   32
#define NTILE (KD / BK)      // 32
#define ASTR 36              // uint2 per A row  (banks 8g+2t: conflict-free)
#define BSTR 116             // uint2 per B k-row (banks 8t+2g: conflict-free)
#define SM_A_BYTES (64 * ASTR * 8)    // 18432
#define SM_B_BYTES (32 * BSTR * 8)    // 29696

// softmaxed conv weights, [m = t*16+b][o = h*7+k]
__device__ float g_wsm[(size_t)MM * NN];

__device__ __forceinline__ unsigned f2tf(float v) {
    unsigned r; asm("cvt.rna.tf32.f32 %0, %1;" : "=r"(r) : "f"(v)); return r;
}
__device__ __forceinline__ uint2 split_tf32(float v) {
    unsigned hi = f2tf(v);
    unsigned lo = f2tf(v - __uint_as_float(hi));
    return make_uint2(hi, lo);
}
__device__ __forceinline__ void mma_tf32(float* c, const unsigned* a, const unsigned* b) {
    asm volatile(
        "mma.sync.aligned.m16n8k8.row.col.f32.tf32.tf32.f32 "
        "{%0,%1,%2,%3}, {%4,%5,%6,%7}, {%8,%9}, {%0,%1,%2,%3};"
        : "+f"(c[0]), "+f"(c[1]), "+f"(c[2]), "+f"(c[3])
        : "r"(a[0]), "r"(a[1]), "r"(a[2]), "r"(a[3]), "r"(b[0]), "r"(b[1]));
}

// ---------------------------------------------------------------------------
// Tensor-core GEMM  w = x @ W^T (16384 x 112 x 1024), 3xTF32, smem-staged
// pre-split tiles shared by the block's 4 warps. Fused masked softmax.
// ---------------------------------------------------------------------------
__global__ __launch_bounds__(128)
void k_gemm_softmax_tc(const float* __restrict__ x,
                       const float* __restrict__ W)
{
    __shared__ __align__(16) char smemRaw[SM_A_BYTES + SM_B_BYTES];  // 47.0 KB
    uint2* As = (uint2*)smemRaw;                      // [row][ASTR]
    uint2* Bs = (uint2*)(smemRaw + SM_A_BYTES);       // [k][BSTR]
    float (*sC)[16][113] = (float (*)[16][113])smemRaw;   // overlay, 28.9 KB

    const int tid  = threadIdx.x;
    const int lane = tid & 31;
    const int wid  = tid >> 5;
    const int gid  = lane >> 2;                // 0..7
    const int tig  = lane & 3;                 // 0..3
    const int mBase = blockIdx.x * BM;
    const int rA0 = wid * 16 + gid;            // warp's fragment rows
    const int rA1 = rA0 + 8;

    float c[14][4];
#pragma unroll
    for (int j = 0; j < 14; j++)
#pragma unroll
        for (int r = 0; r < 4; r++) c[j][r] = 0.f;

    // staging indices: thread covers A elems e=tid+128i (row=e>>5, k=e&31),
    //                  B elems likewise (n=e>>5, k=e&31)
    float aV[16], bV[28];

    // prologue: LDG tile 0
#pragma unroll
    for (int i = 0; i < 16; i++) {
        int e = tid + i * 128;
        aV[i] = x[(size_t)(mBase + (e >> 5)) * KD + (e & 31)];
    }
#pragma unroll
    for (int i = 0; i < 28; i++) {
        int e = tid + i * 128;
        bV[i] = W[(size_t)(e >> 5) * KD + (e & 31)];
    }
#pragma unroll
    for (int i = 0; i < 16; i++) {
        int e = tid + i * 128;
        As[(e >> 5) * ASTR + (e & 31)] = split_tf32(aV[i]);
    }
#pragma unroll
    for (int i = 0; i < 28; i++) {
        int e = tid + i * 128;
        Bs[(e & 31) * BSTR + (e >> 5)] = split_tf32(bV[i]);
    }
    __syncthreads();

    for (int kt = 0; kt < NTILE; kt++) {
        if (kt + 1 < NTILE) {
            const int kOff = (kt + 1) * BK;
#pragma unroll
            for (int i = 0; i < 16; i++) {
                int e = tid + i * 128;
                aV[i] = x[(size_t)(mBase + (e >> 5)) * KD + kOff + (e & 31)];
            }
#pragma unroll
            for (int i = 0; i < 28; i++) {
                int e = tid + i * 128;
                bV[i] = W[(size_t)(e >> 5) * KD + kOff + (e & 31)];
            }
        }

        // ---- compute: 4 k8-steps over the staged tile ----
#pragma unroll
        for (int st = 0; st < 4; st++) {
            const int kb = st * 8;
            uint2 q0 = As[rA0 * ASTR + kb + tig];
            uint2 q1 = As[rA1 * ASTR + kb + tig];
            uint2 q2 = As[rA0 * ASTR + kb + tig + 4];
            uint2 q3 = As[rA1 * ASTR + kb + tig + 4];
            unsigned ahi[4] = { q0.x, q1.x, q2.x, q3.x };
            unsigned alo[4] = { q0.y, q1.y, q2.y, q3.y };

#pragma unroll
            for (int j = 0; j < 14; j++) {
                uint2 p0 = Bs[(kb + tig) * BSTR + j * 8 + gid];
                uint2 p1 = Bs[(kb + tig + 4) * BSTR + j * 8 + gid];
                unsigned bhi[2] = { p0.x, p1.x };
                unsigned blo[2] = { p0.y, p1.y };
                mma_tf32(c[j], ahi, bhi);
                mma_tf32(c[j], ahi, blo);
                mma_tf32(c[j], alo, bhi);
            }
        }
        __syncthreads();

        if (kt + 1 < NTILE) {
#pragma unroll
            for (int i = 0; i < 16; i++) {
                int e = tid + i * 128;
                As[(e >> 5) * ASTR + (e & 31)] = split_tf32(aV[i]);
            }
#pragma unroll
            for (int i = 0; i < 28; i++) {
                int e = tid + i * 128;
                Bs[(e & 31) * BSTR + (e >> 5)] = split_tf32(bV[i]);
            }
            __syncthreads();
        }
    }

    // ---- epilogue: dump fragments to per-warp slab (overlaid smem) ----
#pragma unroll
    for (int j = 0; j < 14; j++) {
        sC[wid][gid    ][j * 8 + 2 * tig    ] = c[j][0];
        sC[wid][gid    ][j * 8 + 2 * tig + 1] = c[j][1];
        sC[wid][gid + 8][j * 8 + 2 * tig    ] = c[j][2];
        sC[wid][gid + 8][j * 8 + 2 * tig + 1] = c[j][3];
    }
    __syncwarp();

    // ---- masked softmax: 8 (row, head) pairs per lane ----
#pragma unroll
    for (int i = 0; i < 8; i++) {
        int p   = i * 32 + lane;               // 0..255
        int row = p >> 4;
        int h   = p & 15;
        int m   = mBase + wid * 16 + row;
        int t   = m >> 4;

        const float* fr = &sC[wid][row][h * 7];
        int kmin = PADL - t; if (kmin < 0) kmin = 0;

        float mx = -1e30f;
#pragma unroll
        for (int k = 0; k < 7; k++)
            if (k >= kmin && fr[k] > mx) mx = fr[k];

        float e[7], s = 0.f;
#pragma unroll
        for (int k = 0; k < 7; k++) {
            e[k] = (k >= kmin) ? __expf(fr[k] - mx) : 0.f;
            s += e[k];
        }
        float inv = 1.f / s;
        float* gp = &g_wsm[(size_t)m * NN + h * 7];
#pragma unroll
        for (int k = 0; k < 7; k++)
            gp[k] = e[k] * inv;
    }
}

// ---------------------------------------------------------------------------
// k_out_band: eight consecutive t per block; 14 gather loads feed 8 outputs,
// plus the band scatter for those rows (dense already zeroed by memset).
// ---------------------------------------------------------------------------
__global__ __launch_bounds__(256)
void k_out_band(const float* __restrict__ x,
                float* __restrict__ out,
                float* __restrict__ dense)
{
    const int t0  = blockIdx.x * 8;
    const int b   = blockIdx.y;
    const int tid = threadIdx.x;

    __shared__ float sw[8 * NN];
    for (int e = tid; e < 8 * NN; e += 256) {
        int r = e / NN, idx = e - r * NN;
        sw[e] = g_wsm[(size_t)((t0 + r) * BB + b) * NN + idx];
    }
    __syncthreads();

    const int h = tid >> 4;
    const float4* x4 = (const float4*)x;

    float4 v[14];
#pragma unroll
    for (int k = 0; k < 14; k++) {
        int pos = t0 - PADL + k;
        if (pos < 0) pos = 0;               // weight is exactly 0 there
        v[k] = x4[((size_t)(pos * BB + b) << 8) + tid];
    }

    float4* out4 = (float4*)out;
#pragma unroll
    for (int r = 0; r < 8; r++) {
        const float* wr = &sw[r * NN + h * 7];
        float4 a = make_float4(0.f, 0.f, 0.f, 0.f);
#pragma unroll
        for (int k = 0; k < 7; k++) {
            float wk = wr[k];
            a.x += wk * v[r + k].x;
            a.y += wk * v[r + k].y;
            a.z += wk * v[r + k].z;
            a.w += wk * v[r + k].w;
        }
        out4[((size_t)((t0 + r) * BB + b) << 8) + tid] = a;
    }

    // band scatter for the 8 rows (zeros already laid by memset)
    for (int e = tid; e < 8 * NN; e += 256) {
        int r   = e / NN, idx = e - r * NN;
        int hh  = idx / 7;
        int k   = idx - hh * 7;
        int t   = t0 + r;
        int col = t - PADL + k;
        if (col >= 0)
            dense[((size_t)(b * HH + hh) << 20) + ((size_t)t << 10) + col] = sw[e];
    }
}

// ---------------------------------------------------------------------------
// Serial: tc-gemm -> memset(dense) -> k_out_band.
// ---------------------------------------------------------------------------
extern "C" void kernel_launch(void* const* d_in, const int* in_sizes, int n_in,
                              void* d_out, int out_size)
{
    const float* x = (const float*)d_in[0];   // (T, B, C) fp32
    const float* W = (const float*)d_in[1];   // (H*K, C)  fp32
    float* out   = (float*)d_out;
    float* dense = out + (size_t)MM * CC;

    k_gemm_softmax_tc<<<MM / BM, 128>>>(x, W);
    cudaMemsetAsync(dense, 0, DENSE_BYTES);
    dim3 g2(TT / 8, BB);
    k_out_band<<<g2, 256>>>(x, out, dense);
}

// round 17
// speedup vs baseline: 1.2205x; 1.0148x over previous
#include <cuda_runtime.h>

#define TT   1024
#define BB   16
#define CC   1024
#define HH   16
#define KW   7
#define PADL 6
#define MM   (TT * BB)       // 16384
#define NN   (HH * KW)       // 112
#define KD   1024

#define BM 64
#define BK 32
#define KHALF 512
#define NTILE_H (KHALF / BK)                        // 16
#define MTILES  (MM / BM)                           // 256
#define DENSE_BYTES ((size_t)BB * HH * TT * TT * 4) // 1 GiB

#define ASTR 66       // floats per p-row of A tile
#define BSTR 33       // floats per o-row of B tile (bank 7tx+7j+p: conflict-free)

// partial logits per k-half
__device__ float g_part[2][(size_t)MM * NN];

typedef unsigned long long ull;
__device__ __forceinline__ ull pk2(float lo, float hi) {
    ull r; asm("mov.b64 %0,{%1,%2};" : "=l"(r) : "f"(lo), "f"(hi)); return r;
}
__device__ __forceinline__ void upk2(ull v, float& lo, float& hi) {
    asm("mov.b64 {%0,%1},%2;" : "=f"(lo), "=f"(hi) : "l"(v));
}
__device__ __forceinline__ void fma2(ull& d, ull a, ull b) {
    asm("fma.rn.f32x2 %0,%1,%2,%3;" : "=l"(d) : "l"(a), "l"(b), "l"(d));
}

// ---------------------------------------------------------------------------
// k_gemm_partial (R14, measured 109us): grid (256, 2). Block (bx, ky)
// computes K-half ky of rows [64bx, 64bx+64) x 112 outputs -> g_part[ky].
// ---------------------------------------------------------------------------
__global__ __launch_bounds__(128, 4)
void k_gemm_partial(const float* __restrict__ x,
                    const float* __restrict__ W)
{
    __shared__ __align__(16) float Asf[BK * ASTR];   //  8448 B, [p][m]
    __shared__ __align__(16) float Bsf[NN * BSTR];   // 14784 B, [o][p]

    const int tid   = threadIdx.x;
    const int tx    = tid & 15;      // head
    const int ty    = tid >> 4;      // 0..7, rows 8ty..8ty+7
    const int mBase = blockIdx.x * BM;
    const int ky    = blockIdx.y;    // k-half
    const int kOff  = ky * KHALF;

    const int kk  = tid & 31;        // loader column
    const int ldr = tid >> 5;        // loader row phase 0..3

    const float* pa = x + (size_t)(mBase + ldr) * KD + kOff + kk;
    const float* pb = W + (size_t)ldr * KD + kOff + kk;

    ull acc[7][4];
#pragma unroll
    for (int j = 0; j < 7; j++)
#pragma unroll
        for (int r = 0; r < 4; r++) acc[j][r] = 0ull;

    float aReg[16], bReg[28];

    // prologue: tile 0
#pragma unroll
    for (int rr = 0; rr < 16; rr++) aReg[rr] = pa[rr * 4 * KD];
#pragma unroll
    for (int oo = 0; oo < 28; oo++) bReg[oo] = pb[oo * 4 * KD];
#pragma unroll
    for (int rr = 0; rr < 16; rr++) Asf[kk * ASTR + ldr + rr * 4] = aReg[rr];
#pragma unroll
    for (int oo = 0; oo < 28; oo++) Bsf[(ldr + oo * 4) * BSTR + kk] = bReg[oo];
    __syncthreads();

    for (int kt = 1; kt <= NTILE_H; kt++) {
        const int k0 = kt * BK;
        if (kt < NTILE_H) {
#pragma unroll
            for (int rr = 0; rr < 16; rr++) aReg[rr] = pa[rr * 4 * KD + k0];
#pragma unroll
            for (int oo = 0; oo < 28; oo++) bReg[oo] = pb[oo * 4 * KD + k0];
        }

#pragma unroll 4
        for (int p = 0; p < BK; p++) {
            const float* ap = &Asf[p * ASTR + 8 * ty];
            ull a0 = *(const ull*)(ap + 0);
            ull a1 = *(const ull*)(ap + 2);
            ull a2 = *(const ull*)(ap + 4);
            ull a3 = *(const ull*)(ap + 6);
#pragma unroll
            for (int j = 0; j < 7; j++) {
                float b = Bsf[(tx * 7 + j) * BSTR + p];
                ull bb = pk2(b, b);
                fma2(acc[j][0], a0, bb);
                fma2(acc[j][1], a1, bb);
                fma2(acc[j][2], a2, bb);
                fma2(acc[j][3], a3, bb);
            }
        }
        __syncthreads();

        if (kt < NTILE_H) {
#pragma unroll
            for (int rr = 0; rr < 16; rr++) Asf[kk * ASTR + ldr + rr * 4] = aReg[rr];
#pragma unroll
            for (int oo = 0; oo < 28; oo++) Bsf[(ldr + oo * 4) * BSTR + kk] = bReg[oo];
            __syncthreads();
        }
    }

    // store partial logits
    float* gp0 = &g_part[ky][(size_t)(mBase + ty * 8) * NN + tx * 7];
#pragma unroll
    for (int rp = 0; rp < 4; rp++) {
        float f0[7], f1[7];
#pragma unroll
        for (int j = 0; j < 7; j++) upk2(acc[j][rp], f0[j], f1[j]);
        float* ga = gp0 + (size_t)(rp * 2 + 0) * NN;
        float* gb = gp0 + (size_t)(rp * 2 + 1) * NN;
#pragma unroll
        for (int k = 0; k < 7; k++) { ga[k] = f0[k]; gb[k] = f1[k]; }
    }
}

// ---------------------------------------------------------------------------
// k_out_band_sm: per (t0, b) block of 8 consecutive t:
//   1) load the two K-half partials for its 8 rows, sum into smem
//   2) masked softmax in smem (threads 0..127, one (row, head) each;
//      bank pattern 112r+7h mod 32 covers all 32 banks -> conflict-free)
//   3) out[t,b,:] = sum_k w * x[clamp(t-6+k), b, :]   (x is L2-hot: the
//      gemm just streamed all 64MB of x through the 126MB L2)
//   4) band scatter into dense (zeroed up-front by the memset)
// ---------------------------------------------------------------------------
__global__ __launch_bounds__(256)
void k_out_band_sm(const float* __restrict__ x,
                   float* __restrict__ out,
                   float* __restrict__ dense)
{
    const int t0  = blockIdx.x * 8;
    const int b   = blockIdx.y;
    const int tid = threadIdx.x;

    __shared__ float sw[8 * NN];

    // 1) reduce the two K-half partials for rows t0..t0+7
    for (int e = tid; e < 8 * NN; e += 256) {
        int r = e / NN, idx = e - r * NN;
        size_t off = (size_t)((t0 + r) * BB + b) * NN + idx;
        sw[e] = g_part[0][off] + g_part[1][off];
    }

    // issue the x gather loads early (independent of sw)
    const float4* x4 = (const float4*)x;
    float4 v[14];
#pragma unroll
    for (int k = 0; k < 14; k++) {
        int pos = t0 - PADL + k;
        if (pos < 0) pos = 0;               // weight is exactly 0 there
        v[k] = x4[((size_t)(pos * BB + b) << 8) + tid];
    }
    __syncthreads();

    // 2) masked softmax: thread tid<128 owns (row = tid/16, head = tid%16)
    if (tid < 128) {
        int r = tid >> 4;
        int h = tid & 15;
        int t = t0 + r;
        float* f = &sw[r * NN + h * 7];

        int kmin = PADL - t; if (kmin < 0) kmin = 0;
        float mx = -1e30f;
#pragma unroll
        for (int k = 0; k < 7; k++)
            if (k >= kmin && f[k] > mx) mx = f[k];

        float e[7], s = 0.f;
#pragma unroll
        for (int k = 0; k < 7; k++) {
            e[k] = (k >= kmin) ? __expf(f[k] - mx) : 0.f;
            s += e[k];
        }
        float inv = 1.f / s;
#pragma unroll
        for (int k = 0; k < 7; k++)
            f[k] = e[k] * inv;
    }
    __syncthreads();

    // 3) gather-weighted output
    const int h = tid >> 4;
    float4* out4 = (float4*)out;
#pragma unroll
    for (int r = 0; r < 8; r++) {
        const float* wr = &sw[r * NN + h * 7];
        float4 a = make_float4(0.f, 0.f, 0.f, 0.f);
#pragma unroll
        for (int k = 0; k < 7; k++) {
            float wk = wr[k];
            a.x += wk * v[r + k].x;
            a.y += wk * v[r + k].y;
            a.z += wk * v[r + k].z;
            a.w += wk * v[r + k].w;
        }
        out4[((size_t)((t0 + r) * BB + b) << 8) + tid] = a;
    }

    // 4) band scatter (zeros already laid)
    for (int e = tid; e < 8 * NN; e += 256) {
        int r   = e / NN, idx = e - r * NN;
        int hh  = idx / 7;
        int k   = idx - hh * 7;
        int t   = t0 + r;
        int col = t - PADL + k;
        if (col >= 0)
            dense[((size_t)(b * HH + hh) << 20) + ((size_t)t << 10) + col] = sw[e];
    }
}

// ---------------------------------------------------------------------------
// Serial: memset(dense) FIRST, then gemm, then k_out_band_sm.
// The memset no longer evicts x between the gemm and the gather kernel.
// ---------------------------------------------------------------------------
extern "C" void kernel_launch(void* const* d_in, const int* in_sizes, int n_in,
                              void* d_out, int out_size)
{
    const float* x = (const float*)d_in[0];   // (T, B, C) fp32
    const float* W = (const float*)d_in[1];   // (H*K, C)  fp32
    float* out   = (float*)d_out;
    float* dense = out + (size_t)MM * CC;

    cudaMemsetAsync(dense, 0, DENSE_BYTES);
    dim3 gg(MTILES, 2);
    k_gemm_partial<<<gg, 128>>>(x, W);
    dim3 g2(TT / 8, BB);
    k_out_band_sm<<<g2, 256>>>(x, out, dense);
}